// round 17
// baseline (speedup 1.0000x reference)
#include <cuda_runtime.h>
#include <cuda_fp16.h>
#include <math.h>
#include <stdint.h>

// Problem constants.
constexpr int B  = 4;
constexpr int T  = 1024;
constexpr int E  = 1024;
constexpr int H  = 16;
constexpr int Dh = 64;
constexpr int M  = B * T;   // 4096

constexpr float LOG2E = 1.4426950408889634f;

// Scratch (__device__ globals; no allocations allowed). Zero-initialized.
__device__ __half g_q[M * E];        // Q projection (pre-scaled by 0.125*log2e)
__device__ __half g_k[M * E];        // K projection, fp16
__device__ __half g_v[M * E];        // V projection, fp16
__device__ __half g_ctxh[M * E];     // attention output, fp16
__device__ __half g_xh[M * E];       // fp16 X
__device__ __half g_wh[4 * E * E];   // fp16 Wq,Wk,Wv,Wo
__device__ __half g_mh[B * T * T];   // fp16 mask * log2e (zero chunks never written)
__device__ int    g_mask_nz;         // 0 while the mask is identically zero

// ---------------------------------------------------------------------------
// Helpers (family-generic PTX only: mma.sync, ldmatrix, cp.async).
// ---------------------------------------------------------------------------
__device__ __forceinline__ uint32_t smem_u32(const void* p) {
    uint32_t a;
    asm("{ .reg .u64 t; cvta.to.shared.u64 t, %1; cvt.u32.u64 %0, t; }" : "=r"(a) : "l"(p));
    return a;
}
// pack {lo=a, hi=b} as fp16x2
__device__ __forceinline__ uint32_t f16x2(float a, float b) {
    uint32_t u;
    asm("cvt.rn.f16x2.f32 %0, %1, %2;" : "=r"(u) : "f"(b), "f"(a));
    return u;
}

__device__ __forceinline__ void mma_f16(float c[4], const uint32_t a[4],
                                        const uint32_t b0, const uint32_t b1)
{
    asm volatile(
        "mma.sync.aligned.m16n8k16.row.col.f32.f16.f16.f32 "
        "{%0,%1,%2,%3}, {%4,%5,%6,%7}, {%8,%9}, {%0,%1,%2,%3};"
        : "+f"(c[0]), "+f"(c[1]), "+f"(c[2]), "+f"(c[3])
        : "r"(a[0]), "r"(a[1]), "r"(a[2]), "r"(a[3]), "r"(b0), "r"(b1));
}

#define LDMX4(r0, r1, r2, r3, addr)                                        \
    asm volatile("ldmatrix.sync.aligned.m8n8.x4.shared.b16 {%0,%1,%2,%3}, [%4];" \
        : "=r"(r0), "=r"(r1), "=r"(r2), "=r"(r3) : "r"(addr))
#define LDMX4T(r0, r1, r2, r3, addr)                                       \
    asm volatile("ldmatrix.sync.aligned.m8n8.x4.trans.shared.b16 {%0,%1,%2,%3}, [%4];" \
        : "=r"(r0), "=r"(r1), "=r"(r2), "=r"(r3) : "r"(addr))

#define CP16(dst, src) \
    asm volatile("cp.async.cg.shared.global [%0], [%1], 16;" :: "r"(dst), "l"(src))
#define CP_COMMIT() asm volatile("cp.async.commit_group;" ::: "memory")
#define CP_WAIT(n)  asm volatile("cp.async.wait_group %0;" :: "n"(n) : "memory")
#define EX2F16X2(out, in) \
    asm("ex2.approx.f16x2 %0, %1;" : "=r"(out) : "r"(in))

// ---------------------------------------------------------------------------
// fp16 GEMM: BK=64, 3 stages, one sync/iter, FRAGMENT DOUBLE-BUFFERING:
// fragments for fk+1 are ldmatrix'd while the mma for fk executes, hiding
// shared-memory latency under tensor work.
//   C[m][n] = (sum_k A[m][k]*W[n][k] + bias[n]) * scale
// MODE: 0 = fp32 out, 2 = fp16 out.
// ---------------------------------------------------------------------------
constexpr int GA_BYTES = 128 * 128;         // 16384 (128 rows x 64 fp16)
constexpr int GSTG     = 2 * GA_BYTES;      // 32768
constexpr int GEMM_SMEM = 3 * GSTG;         // 98304
constexpr int GITERS   = E / 64;            // 16

template <int MODE>
__device__ __forceinline__ void gemm_hp(
    const __half* __restrict__ A, const __half* __restrict__ W,
    const float* __restrict__ bias, void* __restrict__ Cout, float scale)
{
    extern __shared__ __align__(16) char gsm[];
    const uint32_t sb = smem_u32(gsm);

    const int tid  = threadIdx.x;
    const int lane = tid & 31;
    const int wid  = tid >> 5;
    const int wm   = wid >> 2;
    const int wn   = wid & 3;
    const int bm   = blockIdx.y * 128;
    const int bn   = blockIdx.x * 128;

    const int frow = tid >> 3;
    const int fc   = tid & 7;
    const __half* Asrc[4];
    const __half* Wsrc[4];
    uint32_t doff[4];
#pragma unroll
    for (int i = 0; i < 4; i++) {
        const int row = frow + 32 * i;
        Asrc[i] = A + (size_t)(bm + row) * E + fc * 8;
        Wsrc[i] = W + (size_t)(bn + row) * E + fc * 8;
        doff[i] = row * 128 + ((fc ^ (row & 7)) * 16);
    }

    const int rA = lane & 15, hA = lane >> 4;
    const int rB = (lane & 7) | ((lane & 16) >> 1);
    const int hB = (lane >> 3) & 1;
    int arow[4], axor[4];
#pragma unroll
    for (int im = 0; im < 4; im++) {
        arow[im] = wm * 64 + im * 16 + rA;
        axor[im] = arow[im] & 7;
    }
    int brow[2], bxor[2];
#pragma unroll
    for (int p = 0; p < 2; p++) {
        brow[p] = wn * 32 + p * 16 + rB;
        bxor[p] = brow[p] & 7;
    }

    float c[4][4][4];
#pragma unroll
    for (int i = 0; i < 4; i++)
#pragma unroll
        for (int j = 0; j < 4; j++)
#pragma unroll
            for (int r = 0; r < 4; r++) c[i][j][r] = 0.0f;

#pragma unroll
    for (int st = 0; st < 2; st++) {
        const uint32_t base = st * GSTG;
        const int koff = st * 64;
#pragma unroll
        for (int i = 0; i < 4; i++) {
            CP16(sb + base + doff[i],            Asrc[i] + koff);
            CP16(sb + base + GA_BYTES + doff[i], Wsrc[i] + koff);
        }
        CP_COMMIT();
    }

    int scur = 0, snxt = 2;
    for (int it = 0; it < GITERS; it++) {
        if (it >= GITERS - 1) CP_WAIT(0);
        else                  CP_WAIT(1);
        __syncthreads();   // single barrier per iter

        if (it + 2 < GITERS) {
            const uint32_t base = snxt * GSTG;
            const int koff = (it + 2) * 64;
#pragma unroll
            for (int i = 0; i < 4; i++) {
                CP16(sb + base + doff[i],            Asrc[i] + koff);
                CP16(sb + base + GA_BYTES + doff[i], Wsrc[i] + koff);
            }
            CP_COMMIT();
        }

        const uint32_t abase = sb + scur * GSTG;
        const uint32_t bbase = abase + GA_BYTES;

        // Fragment double buffers: load fk=0, then prefetch fk+1 under mma(fk).
        uint32_t a[2][4][4], b[2][4][2];
#pragma unroll
        for (int im = 0; im < 4; im++) {
            const int sw = hA ^ axor[im];
            LDMX4(a[0][im][0], a[0][im][1], a[0][im][2], a[0][im][3],
                  abase + arow[im] * 128 + sw * 16);
        }
#pragma unroll
        for (int p = 0; p < 2; p++) {
            const int sw = hB ^ bxor[p];
            LDMX4(b[0][2 * p][0], b[0][2 * p][1], b[0][2 * p + 1][0], b[0][2 * p + 1][1],
                  bbase + brow[p] * 128 + sw * 16);
        }

#pragma unroll
        for (int fk = 0; fk < 4; fk++) {
            const int cur = fk & 1, nxt = cur ^ 1;
            if (fk < 3) {
#pragma unroll
                for (int im = 0; im < 4; im++) {
                    const int sw = (2 * (fk + 1) + hA) ^ axor[im];
                    LDMX4(a[nxt][im][0], a[nxt][im][1], a[nxt][im][2], a[nxt][im][3],
                          abase + arow[im] * 128 + sw * 16);
                }
#pragma unroll
                for (int p = 0; p < 2; p++) {
                    const int sw = (2 * (fk + 1) + hB) ^ bxor[p];
                    LDMX4(b[nxt][2 * p][0], b[nxt][2 * p][1],
                          b[nxt][2 * p + 1][0], b[nxt][2 * p + 1][1],
                          bbase + brow[p] * 128 + sw * 16);
                }
            }
#pragma unroll
            for (int im = 0; im < 4; im++)
#pragma unroll
                for (int in = 0; in < 4; in++)
                    mma_f16(c[im][in], a[cur][im], b[cur][in][0], b[cur][in][1]);
        }
        scur = (scur == 2) ? 0 : scur + 1;
        snxt = (snxt == 2) ? 0 : snxt + 1;
    }

    const int r0 = lane >> 2;
    const int cl = 2 * (lane & 3);
#pragma unroll
    for (int im = 0; im < 4; im++) {
        const int row = bm + wm * 64 + im * 16 + r0;
#pragma unroll
        for (int in = 0; in < 4; in++) {
            const int col = bn + wn * 32 + in * 8 + cl;
            const float bb0 = bias[col], bb1 = bias[col + 1];
            float o00 = (c[im][in][0] + bb0) * scale;
            float o01 = (c[im][in][1] + bb1) * scale;
            float o10 = (c[im][in][2] + bb0) * scale;
            float o11 = (c[im][in][3] + bb1) * scale;
            if (MODE == 2) {
                __half* C = (__half*)Cout;
                *(uint32_t*)&C[(size_t)row * E + col]       = f16x2(o00, o01);
                *(uint32_t*)&C[(size_t)(row + 8) * E + col] = f16x2(o10, o11);
            } else {
                float* C = (float*)Cout;
                *(float2*)&C[(size_t)row * E + col]       = make_float2(o00, o01);
                *(float2*)&C[(size_t)(row + 8) * E + col] = make_float2(o10, o11);
            }
        }
    }
}

__global__ __launch_bounds__(256) void qkv_mma_kernel(
    const float* __restrict__ bq, const float* __restrict__ bk,
    const float* __restrict__ bv)
{
    const int z = blockIdx.z;
    const __half* W   = g_wh + (size_t)z * E * E;
    const float* bias = (z == 0) ? bq : ((z == 1) ? bk : bv);
    __half*      C    = (z == 0) ? g_q : ((z == 1) ? g_k : g_v);
    const float scale = (z == 0) ? 0.125f * LOG2E : 1.0f;
    gemm_hp<2>(g_xh, W, bias, (void*)C, scale);
}

__global__ __launch_bounds__(256) void oproj_mma_kernel(
    const float* __restrict__ bo, float* __restrict__ out)
{
    gemm_hp<0>(g_ctxh, g_wh + (size_t)3 * E * E, bo, (void*)out, 1.0f);
}

// ---------------------------------------------------------------------------
// fp16 pre-convert: X, 4 weights, mask (scaled by log2e, zero-skip + flag).
// ---------------------------------------------------------------------------
__global__ __launch_bounds__(256) void cvt_kernel(
    const float* __restrict__ x,  const float* __restrict__ wq,
    const float* __restrict__ wk, const float* __restrict__ wv,
    const float* __restrict__ wo, const float* __restrict__ mask)
{
    const int i = blockIdx.x * 256 + threadIdx.x;
    if (blockIdx.y == 5) {
        const int n4 = B * T * T / 4;
        bool nz = false;
        if (i < n4) {
            float4 v = ((const float4*)mask)[i];
            nz = (v.x != 0.0f) | (v.y != 0.0f) | (v.z != 0.0f) | (v.w != 0.0f);
            if (nz) {
                uint2 o = {f16x2(v.x * LOG2E, v.y * LOG2E),
                           f16x2(v.z * LOG2E, v.w * LOG2E)};
                *(uint2*)&g_mh[(size_t)i * 4] = o;
            }
        }
        if (__ballot_sync(0xffffffffu, nz) && (threadIdx.x & 31) == 0)
            atomicOr(&g_mask_nz, 1);
        return;
    }
    const float* src; __half* dst; int n4;
    switch (blockIdx.y) {
        case 0:  src = x;  dst = g_xh;             n4 = M * E / 4; break;
        case 1:  src = wq; dst = g_wh + 0 * E * E; n4 = E * E / 4; break;
        case 2:  src = wk; dst = g_wh + 1 * E * E; n4 = E * E / 4; break;
        case 3:  src = wv; dst = g_wh + 2 * E * E; n4 = E * E / 4; break;
        default: src = wo; dst = g_wh + 3 * E * E; n4 = E * E / 4; break;
    }
    if (i < n4) {
        float4 v = ((const float4*)src)[i];
        uint2 o = {f16x2(v.x, v.y), f16x2(v.z, v.w)};
        *(uint2*)&dst[(size_t)i * 4] = o;
    }
}

// ---------------------------------------------------------------------------
// Tensor-core flash attention (R16 config — measured best): 2 CTAs/SM,
// single mask buffer (adaptive), Q staged in V buf1, register-resident P,
// f16x2 exp2.
// ---------------------------------------------------------------------------
constexpr int KBUF    = 128 * 128;                  // 16384 (fp16 tile)
constexpr int SM_K    = 0;                          // 2 bufs
constexpr int SM_V    = 2 * KBUF;                   // 32768, 2 bufs
constexpr int SM_M    = SM_V + 2 * KBUF;            // 65536, single buf
constexpr int MROWW   = 68;                         // mask row words (64 + pad)
constexpr int MBUF    = 128 * MROWW * 4;            // 34816
constexpr int AT_SMEM = SM_M + MBUF;                // 100352
constexpr int NTILES  = T / 128;                    // 8

__global__ __launch_bounds__(256, 2) void attn_mma_kernel()
{
    extern __shared__ __align__(16) char sm[];
    const uint32_t sb = smem_u32(sm);

    const int tid  = threadIdx.x;
    const int lane = tid & 31;
    const int w    = tid >> 5;
    const int r    = lane >> 2;
    const int j    = lane & 3;
    const int q0   = blockIdx.x * 128;
    const int h    = blockIdx.y;
    const int b    = blockIdx.z;

    const bool usemask = (g_mask_nz != 0);   // uniform across the grid

    // K/V fill coords.
    uint32_t kdst[4], vdst[4];
    const __half *ksrc[4], *vsrc[4];
#pragma unroll
    for (int i = 0; i < 4; i++) {
        const int idx = tid + 256 * i;
        const int row = idx >> 3, vc = idx & 7;
        const uint32_t soff = row * 128 + ((vc ^ (row & 7)) * 16);
        kdst[i] = sb + SM_K + soff;
        vdst[i] = sb + SM_V + soff;
        const size_t g = (size_t)(b * T + row) * E + h * Dh + vc * 8;
        ksrc[i] = &g_k[g];
        vsrc[i] = &g_v[g];
    }
    // Mask fill coords (single buffer).
    uint32_t mdst[8];
    const __half* msrc[8];
#pragma unroll
    for (int i = 0; i < 8; i++) {
        const int idx = tid + 256 * i;
        const int row = idx >> 4, mc = idx & 15;
        mdst[i] = sb + SM_M + row * (MROWW * 4) + mc * 16;
        msrc[i] = &g_mh[((size_t)b * T + q0 + row) * T + mc * 8];
    }

    // Prologue group: K(0), V(0) -> buf0; Q -> V buf1.
#pragma unroll
    for (int i = 0; i < 4; i++) {
        CP16(kdst[i], ksrc[i]);
        CP16(vdst[i], vsrc[i]);
        const int idx = tid + 256 * i;
        const int row = idx >> 3, vc = idx & 7;
        CP16(sb + SM_V + KBUF + row * 128 + ((vc ^ (row & 7)) * 16),
             &g_q[(size_t)(b * T + q0 + row) * E + h * Dh + vc * 8]);
    }
    CP_COMMIT();
    CP_WAIT(0);
    __syncthreads();

    // Q A-frags via ldmatrix from V buf1.
    const int rA = lane & 15, hA = lane >> 4;
    uint32_t qa[4][4];
    {
        const int qrow = w * 16 + rA;
        const uint32_t qb = sb + SM_V + KBUF + qrow * 128;
        const int qx = qrow & 7;
#pragma unroll
        for (int fk = 0; fk < 4; fk++) {
            const int sw = (2 * fk + hA) ^ qx;
            LDMX4(qa[fk][0], qa[fk][1], qa[fk][2], qa[fk][3], qb + sw * 16);
        }
    }

    // K ldmatrix lane geometry.
    const int rB = (lane & 7) | ((lane & 16) >> 1);
    const int hB = (lane >> 3) & 1;
    int krow[8], kxor[8];
#pragma unroll
    for (int p = 0; p < 8; p++) {
        krow[p] = p * 16 + rB;
        kxor[p] = krow[p] & 7;
    }
    // V trans-ldmatrix lane geometry.
    const int i8     = lane & 7;
    const int mm     = lane >> 3;
    const int kv_off = i8 + 8 * (mm & 1);
    const int m1     = mm >> 1;

    const uint32_t moff0 = (w * 16 + r) * MROWW + j;
    const uint32_t moff1 = moff0 + 8 * MROWW;
    const __half2* Mw = (const __half2*)(sm + SM_M);

    float oo[8][4];
#pragma unroll
    for (int fn = 0; fn < 8; fn++)
#pragma unroll
        for (int k = 0; k < 4; k++) oo[fn][k] = 0.0f;

    const float NEG_INF = __int_as_float(0xff800000u);
    float mrow0 = NEG_INF, mrow1 = NEG_INF;
    float lrow0 = 0.0f,    lrow1 = 0.0f;

    for (int t = 0; t < NTILES; t++) {
        const int cur = t & 1;
        CP_WAIT(0);
        __syncthreads();

        if (usemask) {
#pragma unroll
            for (int i = 0; i < 8; i++) CP16(mdst[i], msrc[i] + (size_t)t * 128);
            CP_COMMIT();
        }
        const bool more = (t + 1 < NTILES);
        if (more) {
            const int alt = (t + 1) & 1;
            const size_t soff = (size_t)(t + 1) * 128 * E;
#pragma unroll
            for (int i = 0; i < 4; i++) {
                CP16(kdst[i] + alt * KBUF, ksrc[i] + soff);
                CP16(vdst[i] + alt * KBUF, vsrc[i] + soff);
            }
            CP_COMMIT();
        }

        const uint32_t kb  = sb + SM_K + cur * KBUF;
        const uint32_t vtb = sb + SM_V + cur * KBUF;

        // S = Q K^T.
        float sc[16][4];
#pragma unroll
        for (int fn = 0; fn < 16; fn++)
#pragma unroll
            for (int k = 0; k < 4; k++) sc[fn][k] = 0.0f;

#pragma unroll
        for (int fk = 0; fk < 4; fk++) {
#pragma unroll
            for (int p = 0; p < 8; p++) {
                uint32_t k0, k1, k2, k3;
                const int sw = (2 * fk + hB) ^ kxor[p];
                LDMX4(k0, k1, k2, k3, kb + krow[p] * 128 + sw * 16);
                mma_f16(sc[2 * p],     qa[fk], k0, k1);
                mma_f16(sc[2 * p + 1], qa[fk], k2, k3);
            }
        }

        // Mask add (adaptive) + running row max.
        float ml0 = NEG_INF, ml1 = NEG_INF;
        if (usemask) {
            if (more) CP_WAIT(1); else CP_WAIT(0);
            __syncthreads();
#pragma unroll
            for (int fn = 0; fn < 16; fn++) {
                float2 mk0 = __half22float2(Mw[moff0 + 4 * fn]);
                float2 mk1 = __half22float2(Mw[moff1 + 4 * fn]);
                sc[fn][0] += mk0.x; sc[fn][1] += mk0.y;
                sc[fn][2] += mk1.x; sc[fn][3] += mk1.y;
                ml0 = fmaxf(ml0, fmaxf(sc[fn][0], sc[fn][1]));
                ml1 = fmaxf(ml1, fmaxf(sc[fn][2], sc[fn][3]));
            }
        } else {
#pragma unroll
            for (int fn = 0; fn < 16; fn++) {
                ml0 = fmaxf(ml0, fmaxf(sc[fn][0], sc[fn][1]));
                ml1 = fmaxf(ml1, fmaxf(sc[fn][2], sc[fn][3]));
            }
        }
        ml0 = fmaxf(ml0, __shfl_xor_sync(0xffffffffu, ml0, 1));
        ml0 = fmaxf(ml0, __shfl_xor_sync(0xffffffffu, ml0, 2));
        ml1 = fmaxf(ml1, __shfl_xor_sync(0xffffffffu, ml1, 1));
        ml1 = fmaxf(ml1, __shfl_xor_sync(0xffffffffu, ml1, 2));

        const float mnew0 = fmaxf(mrow0, ml0);
        const float mnew1 = fmaxf(mrow1, ml1);
        const float alpha0 = exp2f(mrow0 - mnew0);
        const float alpha1 = exp2f(mrow1 - mnew1);
        mrow0 = mnew0; mrow1 = mnew1;

        // exp2 pairwise in fp16; P packed directly into PV A-fragments.
        uint32_t pp[16][2];
        float ls0 = 0.0f, ls1 = 0.0f;
#pragma unroll
        for (int fn = 0; fn < 16; fn++) {
            uint32_t u01 = f16x2(sc[fn][0] - mnew0, sc[fn][1] - mnew0);
            uint32_t u23 = f16x2(sc[fn][2] - mnew1, sc[fn][3] - mnew1);
            EX2F16X2(pp[fn][0], u01);
            EX2F16X2(pp[fn][1], u23);
            float2 f01 = __half22float2(*(const __half2*)&pp[fn][0]);
            float2 f23 = __half22float2(*(const __half2*)&pp[fn][1]);
            ls0 += f01.x + f01.y;
            ls1 += f23.x + f23.y;
        }
        ls0 += __shfl_xor_sync(0xffffffffu, ls0, 1);
        ls0 += __shfl_xor_sync(0xffffffffu, ls0, 2);
        ls1 += __shfl_xor_sync(0xffffffffu, ls1, 1);
        ls1 += __shfl_xor_sync(0xffffffffu, ls1, 2);
        lrow0 = lrow0 * alpha0 + ls0;
        lrow1 = lrow1 * alpha1 + ls1;

#pragma unroll
        for (int fn = 0; fn < 8; fn++) {
            oo[fn][0] *= alpha0; oo[fn][1] *= alpha0;
            oo[fn][2] *= alpha1; oo[fn][3] *= alpha1;
        }

        // O += P V.
#pragma unroll
        for (int fk = 0; fk < 8; fk++) {
            uint32_t pa[4] = {pp[2 * fk][0], pp[2 * fk][1],
                              pp[2 * fk + 1][0], pp[2 * fk + 1][1]};
            const uint32_t vrowb = vtb + (uint32_t)(fk * 16 + kv_off) * 128;
#pragma unroll
            for (int fnp = 0; fnp < 4; fnp++) {
                const int chunk = 2 * fnp + m1;
                uint32_t v0, v1, v2, v3;
                LDMX4T(v0, v1, v2, v3, vrowb + ((chunk ^ i8) * 16));
                mma_f16(oo[2 * fnp],     pa, v0, v1);
                mma_f16(oo[2 * fnp + 1], pa, v2, v3);
            }
        }
    }

    // Epilogue: normalize; ctx stored fp16 (feeds fp16 oproj).
    const float inv0 = 1.0f / lrow0;
    const float inv1 = 1.0f / lrow1;
    const size_t row0 = (size_t)(b * T + q0 + w * 16 + r);
#pragma unroll
    for (int fn = 0; fn < 8; fn++) {
        const int d = h * Dh + 8 * fn + 2 * j;
        *(uint32_t*)&g_ctxh[row0 * E + d]       = f16x2(oo[fn][0] * inv0, oo[fn][1] * inv0);
        *(uint32_t*)&g_ctxh[(row0 + 8) * E + d] = f16x2(oo[fn][2] * inv1, oo[fn][3] * inv1);
    }
}

// ---------------------------------------------------------------------------
// Launch.
// ---------------------------------------------------------------------------
extern "C" void kernel_launch(void* const* d_in, const int* in_sizes, int n_in,
                              void* d_out, int out_size)
{
    const float* x    = (const float*)d_in[0];
    const float* mask = (const float*)d_in[1];
    const float* Wq   = (const float*)d_in[2];
    const float* bq   = (const float*)d_in[3];
    const float* Wk   = (const float*)d_in[4];
    const float* bk   = (const float*)d_in[5];
    const float* Wv   = (const float*)d_in[6];
    const float* bv   = (const float*)d_in[7];
    const float* Wo   = (const float*)d_in[8];
    const float* bo   = (const float*)d_in[9];
    float* out = (float*)d_out;

    cudaFuncSetAttribute(qkv_mma_kernel,
                         cudaFuncAttributeMaxDynamicSharedMemorySize, GEMM_SMEM);
    cudaFuncSetAttribute(oproj_mma_kernel,
                         cudaFuncAttributeMaxDynamicSharedMemorySize, GEMM_SMEM);
    cudaFuncSetAttribute(attn_mma_kernel,
                         cudaFuncAttributeMaxDynamicSharedMemorySize, AT_SMEM);
    // Protect 2-CTA smem co-residency on the GEMMs.
    cudaFuncSetAttribute(qkv_mma_kernel,
                         cudaFuncAttributePreferredSharedMemoryCarveout, 100);
    cudaFuncSetAttribute(oproj_mma_kernel,
                         cudaFuncAttributePreferredSharedMemoryCarveout, 100);

    // 1) fp16 pre-convert: X, 4 weights, mask (zero-skip + nonzero flag).
    cvt_kernel<<<dim3(B * T * T / 4 / 256, 6), 256>>>(x, Wq, Wk, Wv, Wo, mask);

    // 2) QKV projections (fp16 mma, BK=64, frag double-buffer): (8, 32, 3).
    qkv_mma_kernel<<<dim3(E / 128, M / 128, 3), 256, GEMM_SMEM>>>(bq, bk, bv);

    // 3) Flash attention (2 CTAs/SM, adaptive mask): (8, 16, 4).
    attn_mma_kernel<<<dim3(T / 128, H, B), 256, AT_SMEM>>>();

    // 4) Output projection: (8, 32) = 256 CTAs, fp32 out.
    oproj_mma_kernel<<<dim3(E / 128, M / 128, 1), 256, GEMM_SMEM>>>(bo, out);
}